// round 5
// baseline (speedup 1.0000x reference)
#include <cuda_runtime.h>
#include <math.h>
#include <stdint.h>

// Problem constants
#define BB 2
#define TT 2048
#define EE 1024
#define HH 16
#define HD 64
#define DFF 4096
#define NTOK (BB*TT)          // 4096
#define BHN (BB*HH)           // 32

// ---------------- scratch (device globals) ----------------
__device__ float g_hres[NTOK*EE];          // LN1 output, full precision (residual)
__device__ float g_h   [NTOK*EE];          // LN1 output, tf32-rounded (GEMM A)
__device__ float g_wqkv[EE*3*EE];          // packed [E,3E], tf32-rounded
__device__ float g_qkv [NTOK*3*EE];        // QKV, tf32-rounded
__device__ float g_o   [NTOK*EE];          // attention out, tf32-rounded
__device__ float g_x2  [NTOK*EE];          // h + proj (full)
__device__ float g_h2res[NTOK*EE];         // LN2 output full (residual)
__device__ float g_h2  [NTOK*EE];          // LN2 output rounded (GEMM A)
__device__ float g_ffn [NTOK*DFF];         // relu(h2@w1+b1), rounded
__device__ float g_wp  [EE*EE];            // w_proj rounded
__device__ float g_w1  [EE*DFF];           // w1 rounded
__device__ float g_w2  [DFF*EE];           // w2 rounded

// ---------------- helpers ----------------
__device__ __forceinline__ uint32_t cvt_tf32(float x) {
    uint32_t r;
    asm("cvt.rna.tf32.f32 %0, %1;" : "=r"(r) : "f"(x));
    return r;
}
__device__ __forceinline__ float cvt_tf32f(float x) {
    return __uint_as_float(cvt_tf32(x));
}
__device__ __forceinline__ void cp16(void* s, const void* g) {
    uint32_t sa = (uint32_t)__cvta_generic_to_shared(s);
    asm volatile("cp.async.cg.shared.global [%0], [%1], 16;" :: "r"(sa), "l"(g));
}
__device__ __forceinline__ void cp_commit() { asm volatile("cp.async.commit_group;"); }
template<int N> __device__ __forceinline__ void cp_wait() {
    asm volatile("cp.async.wait_group %0;" :: "n"(N));
}
__device__ __forceinline__ void mma_tf32(float acc[4], const uint32_t a[4],
                                         uint32_t b0, uint32_t b1) {
    asm volatile(
        "mma.sync.aligned.m16n8k8.row.col.f32.tf32.tf32.f32 "
        "{%0,%1,%2,%3},{%4,%5,%6,%7},{%8,%9},{%0,%1,%2,%3};"
        : "+f"(acc[0]), "+f"(acc[1]), "+f"(acc[2]), "+f"(acc[3])
        : "r"(a[0]), "r"(a[1]), "r"(a[2]), "r"(a[3]), "r"(b0), "r"(b1));
}

// ---------------- LayerNorm: full + rounded outputs ----------------
__global__ void ln_kernel(const float* __restrict__ x,
                          const float* __restrict__ gamma,
                          const float* __restrict__ beta,
                          float* __restrict__ yfull,
                          float* __restrict__ yrnd)
{
    int row = blockIdx.x;
    const float* xr = x + (size_t)row * EE;
    float* yf = yfull + (size_t)row * EE;
    float* yr = yrnd + (size_t)row * EE;
    int tid = threadIdx.x;
    __shared__ float red[256];

    float s = 0.f;
    for (int i = tid; i < EE; i += 256) s += xr[i];
    red[tid] = s; __syncthreads();
    for (int o = 128; o > 0; o >>= 1) { if (tid < o) red[tid] += red[tid + o]; __syncthreads(); }
    float mean = red[0] * (1.0f / EE);
    __syncthreads();

    float v = 0.f;
    for (int i = tid; i < EE; i += 256) { float d = xr[i] - mean; v += d * d; }
    red[tid] = v; __syncthreads();
    for (int o = 128; o > 0; o >>= 1) { if (tid < o) red[tid] += red[tid + o]; __syncthreads(); }
    float inv = rsqrtf(red[0] * (1.0f / EE) + 1e-5f);

    for (int i = tid; i < EE; i += 256) {
        float val = (xr[i] - mean) * inv * gamma[i] + beta[i];
        yf[i] = val;
        yr[i] = cvt_tf32f(val);
    }
}

// ---------------- round weights to tf32 ----------------
__global__ void round_kernel(const float* __restrict__ in, float* __restrict__ out, int n)
{
    int idx = blockIdx.x * blockDim.x + threadIdx.x;
    if (idx < n) out[idx] = cvt_tf32f(in[idx]);
}

// ---------------- pack wq/wk/wv [H,E,hd] -> [E,3E], rounded ----------------
__global__ void pack_w_kernel(const float* __restrict__ wq,
                              const float* __restrict__ wk,
                              const float* __restrict__ wv,
                              float* __restrict__ out)
{
    int idx = blockIdx.x * blockDim.x + threadIdx.x;
    const int total = 3 * EE * EE;
    if (idx >= total) return;
    int part = idx / (EE * EE);
    int rem  = idx % (EE * EE);
    int e = rem / EE;
    int c = rem % EE;
    const float* w = (part == 0) ? wq : (part == 1) ? wk : wv;
    out[(size_t)e * (3 * EE) + part * EE + c] =
        cvt_tf32f(w[(size_t)(c >> 6) * (EE * HD) + (size_t)e * HD + (c & 63)]);
}

// ---------------- tf32 GEMM (R2 structure, CVT-free hot loop) -----------
// Operands MUST be pre-rounded to tf32. Block 128x128x16, 8 warps.
// EPI: 0 = none; 2 = relu(+bias); 3 = +bias +res.  RND: round output to tf32.
template <int EPI, bool RND>
__global__ void __launch_bounds__(256, 2)
mm_tf32(const float* __restrict__ A,
        const float* __restrict__ B,
        const float* __restrict__ bias,
        const float* __restrict__ res,
        float* __restrict__ C,
        int M, int N, int K)
{
    const int BM = 128, BN = 128, BK = 16;
    __shared__ float As[2][BM][BK + 4];
    __shared__ float Bs[2][BK][BN + 8];

    int tid = threadIdx.x;
    int lane = tid & 31, wid = tid >> 5;
    int wm = wid >> 1, wn = wid & 1;
    int g = lane >> 2, c = lane & 3;
    int rowBase = blockIdx.y * BM;
    int colBase = blockIdx.x * BN;

    float acc[2][8][4];
    #pragma unroll
    for (int i = 0; i < 2; i++)
        #pragma unroll
        for (int j = 0; j < 8; j++)
            #pragma unroll
            for (int k = 0; k < 4; k++) acc[i][j][k] = 0.f;

    auto load_stage = [&](int buf, int kk) {
        #pragma unroll
        for (int i = 0; i < 2; i++) {
            int idx = i * 256 + tid;
            int m = idx >> 2, ch = idx & 3;
            cp16(&As[buf][m][ch * 4], A + (size_t)(rowBase + m) * K + kk + ch * 4);
        }
        #pragma unroll
        for (int i = 0; i < 2; i++) {
            int idx = i * 256 + tid;
            int r = idx >> 5, ch = idx & 31;
            cp16(&Bs[buf][r][ch * 4], B + (size_t)(kk + r) * N + colBase + ch * 4);
        }
        cp_commit();
    };

    load_stage(0, 0);
    int nk = K / BK;
    for (int k0 = 0; k0 < nk; k0++) {
        int cur = k0 & 1;
        if (k0 + 1 < nk) { load_stage(cur ^ 1, (k0 + 1) * BK); cp_wait<1>(); }
        else            { cp_wait<0>(); }
        __syncthreads();

        #pragma unroll
        for (int ks = 0; ks < 2; ks++) {
            int kb = ks * 8;
            uint32_t af[2][4];
            #pragma unroll
            for (int mt = 0; mt < 2; mt++) {
                int m0 = wm * 32 + mt * 16;
                af[mt][0] = __float_as_uint(As[cur][m0 + g    ][kb + c    ]);
                af[mt][1] = __float_as_uint(As[cur][m0 + g + 8][kb + c    ]);
                af[mt][2] = __float_as_uint(As[cur][m0 + g    ][kb + c + 4]);
                af[mt][3] = __float_as_uint(As[cur][m0 + g + 8][kb + c + 4]);
            }
            uint32_t bf[8][2];
            #pragma unroll
            for (int nt = 0; nt < 8; nt++) {
                int n0 = wn * 64 + nt * 8;
                bf[nt][0] = __float_as_uint(Bs[cur][kb + c    ][n0 + g]);
                bf[nt][1] = __float_as_uint(Bs[cur][kb + c + 4][n0 + g]);
            }
            #pragma unroll
            for (int mt = 0; mt < 2; mt++)
                #pragma unroll
                for (int nt = 0; nt < 8; nt++)
                    mma_tf32(acc[mt][nt], af[mt], bf[nt][0], bf[nt][1]);
        }
        __syncthreads();
    }

    #pragma unroll
    for (int mt = 0; mt < 2; mt++) {
        int row0 = rowBase + wm * 32 + mt * 16 + g;
        #pragma unroll
        for (int nt = 0; nt < 8; nt++) {
            int col = colBase + wn * 64 + nt * 8 + c * 2;
            float v0 = acc[mt][nt][0], v1 = acc[mt][nt][1];
            float v2 = acc[mt][nt][2], v3 = acc[mt][nt][3];
            if (EPI >= 1) {
                float b0 = bias[col], b1 = bias[col + 1];
                v0 += b0; v1 += b1; v2 += b0; v3 += b1;
            }
            if (EPI == 2) {
                v0 = fmaxf(v0, 0.f); v1 = fmaxf(v1, 0.f);
                v2 = fmaxf(v2, 0.f); v3 = fmaxf(v3, 0.f);
            }
            if (EPI == 3) {
                v0 += res[(size_t)row0 * N + col];
                v1 += res[(size_t)row0 * N + col + 1];
                v2 += res[(size_t)(row0 + 8) * N + col];
                v3 += res[(size_t)(row0 + 8) * N + col + 1];
            }
            if (RND) {
                v0 = cvt_tf32f(v0); v1 = cvt_tf32f(v1);
                v2 = cvt_tf32f(v2); v3 = cvt_tf32f(v3);
            }
            *reinterpret_cast<float2*>(&C[(size_t)row0 * N + col])       = make_float2(v0, v1);
            *reinterpret_cast<float2*>(&C[(size_t)(row0 + 8) * N + col]) = make_float2(v2, v3);
        }
    }
}

// ---------------- fused flash attention (R2 layout; qkv pre-rounded) --------
// grid: (T/64, BHN); block: 128 (4 warps, 16 query rows each)
__global__ void __launch_bounds__(128)
flash_kernel(const float* __restrict__ qkv, float* __restrict__ o)
{
    __shared__ float KP[64][68];   // K tile, then reused as P tile
    __shared__ float Vs[64][72];

    int bh = blockIdx.y;
    int b = bh >> 4, h = bh & 15;
    int rt = gridDim.x - 1 - blockIdx.x;   // heavy CTAs first
    int q0 = rt * 64;

    int tid = threadIdx.x;
    int lane = tid & 31, wid = tid >> 5;
    int g = lane >> 2, c = lane & 3;
    int wbase = wid * 16;

    // Q fragments: pre-rounded; *0.125f is exact (power of two)
    uint32_t qf[8][4];
    const float* Qb = qkv + ((size_t)(b * TT + q0 + wbase)) * (3 * EE) + (size_t)h * HD;
    #pragma unroll
    for (int k8 = 0; k8 < 8; k8++) {
        int kb = k8 * 8;
        qf[k8][0] = __float_as_uint(0.125f * Qb[(size_t)g       * (3 * EE) + kb + c]);
        qf[k8][1] = __float_as_uint(0.125f * Qb[(size_t)(g + 8) * (3 * EE) + kb + c]);
        qf[k8][2] = __float_as_uint(0.125f * Qb[(size_t)g       * (3 * EE) + kb + c + 4]);
        qf[k8][3] = __float_as_uint(0.125f * Qb[(size_t)(g + 8) * (3 * EE) + kb + c + 4]);
    }

    float m0 = -INFINITY, m1 = -INFINITY, l0 = 0.f, l1 = 0.f;
    float oacc[8][4];
    #pragma unroll
    for (int nt = 0; nt < 8; nt++)
        #pragma unroll
        for (int k = 0; k < 4; k++) oacc[nt][k] = 0.f;

    for (int st = 0; st <= rt; st++) {
        __syncthreads();

        // K,V tiles already tf32-rounded: plain vector copy
        const float* Kg = qkv + ((size_t)(b * TT + st * 64)) * (3 * EE) + EE + (size_t)h * HD;
        const float* Vg = Kg + EE;
        #pragma unroll
        for (int i = 0; i < 8; i++) {
            int idx = i * 128 + tid;
            int r = idx >> 4, ch = (idx & 15) * 4;
            *(float4*)&KP[r][ch] = *(const float4*)(Kg + (size_t)r * (3 * EE) + ch);
            *(float4*)&Vs[r][ch] = *(const float4*)(Vg + (size_t)r * (3 * EE) + ch);
        }
        __syncthreads();

        // S = Q @ K^T
        float sacc[8][4];
        #pragma unroll
        for (int nt = 0; nt < 8; nt++)
            #pragma unroll
            for (int k = 0; k < 4; k++) sacc[nt][k] = 0.f;

        #pragma unroll
        for (int k8 = 0; k8 < 8; k8++) {
            int kb = k8 * 8;
            #pragma unroll
            for (int nt = 0; nt < 8; nt++) {
                uint32_t b0 = __float_as_uint(KP[nt * 8 + g][kb + c]);
                uint32_t b1 = __float_as_uint(KP[nt * 8 + g][kb + c + 4]);
                mma_tf32(sacc[nt], qf[k8], b0, b1);
            }
        }

        // causal mask on diagonal tile only
        if (st == rt) {
            int ql0 = wbase + g, ql1 = ql0 + 8;
            #pragma unroll
            for (int nt = 0; nt < 8; nt++) {
                int kl = nt * 8 + 2 * c;
                if (kl     > ql0) sacc[nt][0] = -1e30f;
                if (kl + 1 > ql0) sacc[nt][1] = -1e30f;
                if (kl     > ql1) sacc[nt][2] = -1e30f;
                if (kl + 1 > ql1) sacc[nt][3] = -1e30f;
            }
        }

        // online softmax
        float mx0 = -1e30f, mx1 = -1e30f;
        #pragma unroll
        for (int nt = 0; nt < 8; nt++) {
            mx0 = fmaxf(mx0, fmaxf(sacc[nt][0], sacc[nt][1]));
            mx1 = fmaxf(mx1, fmaxf(sacc[nt][2], sacc[nt][3]));
        }
        mx0 = fmaxf(mx0, __shfl_xor_sync(0xffffffffu, mx0, 1));
        mx0 = fmaxf(mx0, __shfl_xor_sync(0xffffffffu, mx0, 2));
        mx1 = fmaxf(mx1, __shfl_xor_sync(0xffffffffu, mx1, 1));
        mx1 = fmaxf(mx1, __shfl_xor_sync(0xffffffffu, mx1, 2));

        float mn0 = fmaxf(m0, mx0), mn1 = fmaxf(m1, mx1);
        float al0 = __expf(m0 - mn0), al1 = __expf(m1 - mn1);
        m0 = mn0; m1 = mn1;

        float rs0 = 0.f, rs1 = 0.f;
        #pragma unroll
        for (int nt = 0; nt < 8; nt++) {
            float p0 = __expf(sacc[nt][0] - m0);
            float p1 = __expf(sacc[nt][1] - m0);
            float p2 = __expf(sacc[nt][2] - m1);
            float p3 = __expf(sacc[nt][3] - m1);
            sacc[nt][0] = p0; sacc[nt][1] = p1; sacc[nt][2] = p2; sacc[nt][3] = p3;
            rs0 += p0 + p1; rs1 += p2 + p3;
        }
        rs0 += __shfl_xor_sync(0xffffffffu, rs0, 1);
        rs0 += __shfl_xor_sync(0xffffffffu, rs0, 2);
        rs1 += __shfl_xor_sync(0xffffffffu, rs1, 1);
        rs1 += __shfl_xor_sync(0xffffffffu, rs1, 2);
        l0 = l0 * al0 + rs0;
        l1 = l1 * al1 + rs1;

        #pragma unroll
        for (int nt = 0; nt < 8; nt++) {
            oacc[nt][0] *= al0; oacc[nt][1] *= al0;
            oacc[nt][2] *= al1; oacc[nt][3] *= al1;
        }

        // store P into KP (K dead)
        __syncthreads();
        #pragma unroll
        for (int nt = 0; nt < 8; nt++) {
            int col = nt * 8 + 2 * c;
            KP[wbase + g    ][col]     = cvt_tf32f(sacc[nt][0]);
            KP[wbase + g    ][col + 1] = cvt_tf32f(sacc[nt][1]);
            KP[wbase + g + 8][col]     = cvt_tf32f(sacc[nt][2]);
            KP[wbase + g + 8][col + 1] = cvt_tf32f(sacc[nt][3]);
        }
        __syncwarp();

        // O += P @ V
        #pragma unroll
        for (int k8 = 0; k8 < 8; k8++) {
            int kb = k8 * 8;
            uint32_t af[4];
            af[0] = __float_as_uint(KP[wbase + g    ][kb + c]);
            af[1] = __float_as_uint(KP[wbase + g + 8][kb + c]);
            af[2] = __float_as_uint(KP[wbase + g    ][kb + c + 4]);
            af[3] = __float_as_uint(KP[wbase + g + 8][kb + c + 4]);
            #pragma unroll
            for (int nt = 0; nt < 8; nt++) {
                uint32_t b0 = __float_as_uint(Vs[kb + c    ][nt * 8 + g]);
                uint32_t b1 = __float_as_uint(Vs[kb + c + 4][nt * 8 + g]);
                mma_tf32(oacc[nt], af, b0, b1);
            }
        }
    }

    // epilogue: normalize, round (o feeds proj GEMM), write
    float i0 = 1.0f / l0, i1 = 1.0f / l1;
    float* Ob = o + ((size_t)(b * TT + q0 + wbase)) * EE + (size_t)h * HD;
    #pragma unroll
    for (int nt = 0; nt < 8; nt++) {
        int col = nt * 8 + 2 * c;
        *(float2*)&Ob[(size_t)g * EE + col] =
            make_float2(cvt_tf32f(oacc[nt][0] * i0), cvt_tf32f(oacc[nt][1] * i0));
        *(float2*)&Ob[(size_t)(g + 8) * EE + col] =
            make_float2(cvt_tf32f(oacc[nt][2] * i1), cvt_tf32f(oacc[nt][3] * i1));
    }
}

// ---------------- launcher ----------------
extern "C" void kernel_launch(void* const* d_in, const int* in_sizes, int n_in,
                              void* d_out, int out_size)
{
    const float* x      = (const float*)d_in[0];
    const float* wq     = (const float*)d_in[1];
    const float* wk     = (const float*)d_in[2];
    const float* wv     = (const float*)d_in[3];
    const float* w_proj = (const float*)d_in[4];
    const float* b_proj = (const float*)d_in[5];
    const float* gamma1 = (const float*)d_in[6];
    const float* beta1  = (const float*)d_in[7];
    const float* gamma2 = (const float*)d_in[8];
    const float* beta2  = (const float*)d_in[9];
    const float* w1     = (const float*)d_in[10];
    const float* b1     = (const float*)d_in[11];
    const float* w2     = (const float*)d_in[12];
    const float* b2     = (const float*)d_in[13];
    float* out = (float*)d_out;

    float *p_hres, *p_h, *p_wqkv, *p_qkv, *p_o, *p_x2, *p_h2res, *p_h2, *p_ffn;
    float *p_wp, *p_w1, *p_w2;
    cudaGetSymbolAddress((void**)&p_hres,  g_hres);
    cudaGetSymbolAddress((void**)&p_h,     g_h);
    cudaGetSymbolAddress((void**)&p_wqkv,  g_wqkv);
    cudaGetSymbolAddress((void**)&p_qkv,   g_qkv);
    cudaGetSymbolAddress((void**)&p_o,     g_o);
    cudaGetSymbolAddress((void**)&p_x2,    g_x2);
    cudaGetSymbolAddress((void**)&p_h2res, g_h2res);
    cudaGetSymbolAddress((void**)&p_h2,    g_h2);
    cudaGetSymbolAddress((void**)&p_ffn,   g_ffn);
    cudaGetSymbolAddress((void**)&p_wp,    g_wp);
    cudaGetSymbolAddress((void**)&p_w1,    g_w1);
    cudaGetSymbolAddress((void**)&p_w2,    g_w2);

    // 1) LN1 (full + rounded)
    ln_kernel<<<NTOK, 256>>>(x, gamma1, beta1, p_hres, p_h);
    // 2) pack + round weights
    pack_w_kernel<<<(3 * EE * EE) / 256, 256>>>(wq, wk, wv, p_wqkv);
    round_kernel<<<(EE * EE) / 256, 256>>>(w_proj, p_wp, EE * EE);
    round_kernel<<<(EE * DFF) / 256, 256>>>(w1, p_w1, EE * DFF);
    round_kernel<<<(DFF * EE) / 256, 256>>>(w2, p_w2, DFF * EE);
    // 3) QKV = h @ Wqkv (rounded output -> flash)
    mm_tf32<0, true><<<dim3(3 * EE / 128, NTOK / 128), 256>>>(p_h, p_wqkv, nullptr, nullptr, p_qkv, NTOK, 3 * EE, EE);
    // 4-6) fused flash attention
    flash_kernel<<<dim3(TT / 64, BHN), 128>>>(p_qkv, p_o);
    // 7) x2 = hres + O @ w_proj + b_proj (full output -> LN2)
    mm_tf32<3, false><<<dim3(EE / 128, NTOK / 128), 256>>>(p_o, p_wp, b_proj, p_hres, p_x2, NTOK, EE, EE);
    // 8) LN2 (full + rounded)
    ln_kernel<<<NTOK, 256>>>(p_x2, gamma2, beta2, p_h2res, p_h2);
    // 9) ffn = relu(h2 @ w1 + b1) (rounded -> FFN2)
    mm_tf32<2, true><<<dim3(DFF / 128, NTOK / 128), 256>>>(p_h2, p_w1, b1, nullptr, p_ffn, NTOK, DFF, EE);
    // 10) out = h2res + ffn @ w2 + b2
    mm_tf32<3, false><<<dim3(EE / 128, NTOK / 128), 256>>>(p_ffn, p_w2, b2, p_h2res, out, NTOK, EE, DFF);
}

// round 6
// speedup vs baseline: 1.5365x; 1.5365x over previous
#include <cuda_runtime.h>
#include <math.h>
#include <stdint.h>

// Problem constants
#define BB 2
#define TT 2048
#define EE 1024
#define HH 16
#define HD 64
#define DFF 4096
#define NTOK (BB*TT)          // 4096
#define BHN (BB*HH)           // 32

// ---------------- scratch (device globals) ----------------
__device__ float g_h   [NTOK*EE];
__device__ float g_wqkv[EE*3*EE];
__device__ float g_qkv [NTOK*3*EE];
__device__ float g_o   [NTOK*EE];
__device__ float g_x2  [NTOK*EE];
__device__ float g_h2  [NTOK*EE];
__device__ float g_ffn [NTOK*DFF];

// ---------------- helpers ----------------
__device__ __forceinline__ uint32_t cvt_tf32(float x) {
    uint32_t r;
    asm("cvt.rna.tf32.f32 %0, %1;" : "=r"(r) : "f"(x));
    return r;
}
__device__ __forceinline__ float cvt_tf32f(float x) {
    return __uint_as_float(cvt_tf32(x));
}
__device__ __forceinline__ void cp16(void* s, const void* g) {
    uint32_t sa = (uint32_t)__cvta_generic_to_shared(s);
    asm volatile("cp.async.cg.shared.global [%0], [%1], 16;" :: "r"(sa), "l"(g));
}
__device__ __forceinline__ void cp_commit() { asm volatile("cp.async.commit_group;"); }
template<int N> __device__ __forceinline__ void cp_wait() {
    asm volatile("cp.async.wait_group %0;" :: "n"(N));
}
__device__ __forceinline__ void mma_tf32(float acc[4], const uint32_t a[4],
                                         uint32_t b0, uint32_t b1) {
    asm volatile(
        "mma.sync.aligned.m16n8k8.row.col.f32.tf32.tf32.f32 "
        "{%0,%1,%2,%3},{%4,%5,%6,%7},{%8,%9},{%0,%1,%2,%3};"
        : "+f"(acc[0]), "+f"(acc[1]), "+f"(acc[2]), "+f"(acc[3])
        : "r"(a[0]), "r"(a[1]), "r"(a[2]), "r"(a[3]), "r"(b0), "r"(b1));
}

// ---------------- LayerNorm ----------------
__global__ void ln_kernel(const float* __restrict__ x,
                          const float* __restrict__ gamma,
                          const float* __restrict__ beta,
                          float* __restrict__ y)
{
    int row = blockIdx.x;
    const float* xr = x + (size_t)row * EE;
    float* yr = y + (size_t)row * EE;
    int tid = threadIdx.x;
    __shared__ float red[256];

    float s = 0.f;
    for (int i = tid; i < EE; i += 256) s += xr[i];
    red[tid] = s; __syncthreads();
    for (int o = 128; o > 0; o >>= 1) { if (tid < o) red[tid] += red[tid + o]; __syncthreads(); }
    float mean = red[0] * (1.0f / EE);
    __syncthreads();

    float v = 0.f;
    for (int i = tid; i < EE; i += 256) { float d = xr[i] - mean; v += d * d; }
    red[tid] = v; __syncthreads();
    for (int o = 128; o > 0; o >>= 1) { if (tid < o) red[tid] += red[tid + o]; __syncthreads(); }
    float inv = rsqrtf(red[0] * (1.0f / EE) + 1e-5f);

    for (int i = tid; i < EE; i += 256)
        yr[i] = (xr[i] - mean) * inv * gamma[i] + beta[i];
}

// ---------------- pack wq/wk/wv [H,E,hd] -> [E, 3E] ----------------
__global__ void pack_w_kernel(const float* __restrict__ wq,
                              const float* __restrict__ wk,
                              const float* __restrict__ wv,
                              float* __restrict__ out)
{
    int idx = blockIdx.x * blockDim.x + threadIdx.x;
    const int total = 3 * EE * EE;
    if (idx >= total) return;
    int part = idx / (EE * EE);
    int rem  = idx % (EE * EE);
    int e = rem / EE;
    int c = rem % EE;
    const float* w = (part == 0) ? wq : (part == 1) ? wk : wv;
    out[(size_t)e * (3 * EE) + part * EE + c] =
        w[(size_t)(c >> 6) * (EE * HD) + (size_t)e * HD + (c & 63)];
}

// ---------------- tf32 GEMM: BK=32, one sync per K-step -----------
// Block 128x128x32, 8 warps (4x2), warp tile 32x64 via m16n8k8.
// EPI: 0 = none; 2 = relu(+bias); 3 = +bias +res
#define MM_SMEM ((2*128*36 + 2*32*136) * 4)   // 71680 B

template <int EPI>
__global__ void __launch_bounds__(256, 2)
mm_tf32(const float* __restrict__ A,
        const float* __restrict__ B,
        const float* __restrict__ bias,
        const float* __restrict__ res,
        float* __restrict__ C,
        int M, int N, int K)
{
    const int BM = 128, BN = 128, BK = 32;
    extern __shared__ float sm[];
    float (*As)[BM][36]  = reinterpret_cast<float(*)[BM][36]>(sm);
    float (*Bs)[BK][136] = reinterpret_cast<float(*)[BK][136]>(sm + 2 * BM * 36);

    int tid = threadIdx.x;
    int lane = tid & 31, wid = tid >> 5;
    int wm = wid >> 1, wn = wid & 1;
    int g = lane >> 2, c = lane & 3;
    int rowBase = blockIdx.y * BM;
    int colBase = blockIdx.x * BN;

    float acc[2][8][4];
    #pragma unroll
    for (int i = 0; i < 2; i++)
        #pragma unroll
        for (int j = 0; j < 8; j++)
            #pragma unroll
            for (int k = 0; k < 4; k++) acc[i][j][k] = 0.f;

    auto load_stage = [&](int buf, int kk) {
        // A: 128x32 = 1024 16B-chunks; 4 per thread
        #pragma unroll
        for (int i = 0; i < 4; i++) {
            int idx = i * 256 + tid;
            int m = idx >> 3, ch = idx & 7;
            cp16(&As[buf][m][ch * 4], A + (size_t)(rowBase + m) * K + kk + ch * 4);
        }
        // B: 32x128 = 1024 16B-chunks; 4 per thread
        #pragma unroll
        for (int i = 0; i < 4; i++) {
            int idx = i * 256 + tid;
            int r = idx >> 5, ch = idx & 31;
            cp16(&Bs[buf][r][ch * 4], B + (size_t)(kk + r) * N + colBase + ch * 4);
        }
        cp_commit();
    };

    load_stage(0, 0);
    int nk = K / BK;
    for (int k0 = 0; k0 < nk; k0++) {
        cp_wait<0>();            // this warp's share of stage k0 done
        __syncthreads();         // => every warp's share done; prev compute done
        if (k0 + 1 < nk) load_stage((k0 + 1) & 1, (k0 + 1) * BK);

        int cur = k0 & 1;
        #pragma unroll
        for (int ks = 0; ks < 4; ks++) {
            int kb = ks * 8;
            uint32_t af[2][4];
            #pragma unroll
            for (int mt = 0; mt < 2; mt++) {
                int m0 = wm * 32 + mt * 16;
                af[mt][0] = cvt_tf32(As[cur][m0 + g    ][kb + c    ]);
                af[mt][1] = cvt_tf32(As[cur][m0 + g + 8][kb + c    ]);
                af[mt][2] = cvt_tf32(As[cur][m0 + g    ][kb + c + 4]);
                af[mt][3] = cvt_tf32(As[cur][m0 + g + 8][kb + c + 4]);
            }
            uint32_t bf[8][2];
            #pragma unroll
            for (int nt = 0; nt < 8; nt++) {
                int n0 = wn * 64 + nt * 8;
                bf[nt][0] = cvt_tf32(Bs[cur][kb + c    ][n0 + g]);
                bf[nt][1] = cvt_tf32(Bs[cur][kb + c + 4][n0 + g]);
            }
            #pragma unroll
            for (int mt = 0; mt < 2; mt++)
                #pragma unroll
                for (int nt = 0; nt < 8; nt++)
                    mma_tf32(acc[mt][nt], af[mt], bf[nt][0], bf[nt][1]);
        }
    }

    #pragma unroll
    for (int mt = 0; mt < 2; mt++) {
        int row0 = rowBase + wm * 32 + mt * 16 + g;
        #pragma unroll
        for (int nt = 0; nt < 8; nt++) {
            int col = colBase + wn * 64 + nt * 8 + c * 2;
            float v0 = acc[mt][nt][0], v1 = acc[mt][nt][1];
            float v2 = acc[mt][nt][2], v3 = acc[mt][nt][3];
            if (EPI >= 1) {
                float b0 = bias[col], b1 = bias[col + 1];
                v0 += b0; v1 += b1; v2 += b0; v3 += b1;
            }
            if (EPI == 2) {
                v0 = fmaxf(v0, 0.f); v1 = fmaxf(v1, 0.f);
                v2 = fmaxf(v2, 0.f); v3 = fmaxf(v3, 0.f);
            }
            if (EPI == 3) {
                v0 += res[(size_t)row0 * N + col];
                v1 += res[(size_t)row0 * N + col + 1];
                v2 += res[(size_t)(row0 + 8) * N + col];
                v3 += res[(size_t)(row0 + 8) * N + col + 1];
            }
            *reinterpret_cast<float2*>(&C[(size_t)row0 * N + col])       = make_float2(v0, v1);
            *reinterpret_cast<float2*>(&C[(size_t)(row0 + 8) * N + col]) = make_float2(v2, v3);
        }
    }
}

// ---------------- fused flash attention, double-buffered K/V ----------------
// grid: (T/64, BHN); block: 128 (4 warps, 16 query rows each)
#define FL_SMEM ((2*64*68 + 2*64*72) * 4)   // 71680 B

__global__ void __launch_bounds__(128)
flash_kernel(const float* __restrict__ qkv, float* __restrict__ o)
{
    extern __shared__ float fsm[];
    float (*KP)[64][68] = reinterpret_cast<float(*)[64][68]>(fsm);          // K tile -> P tile
    float (*Vs)[64][72] = reinterpret_cast<float(*)[64][72]>(fsm + 2*64*68);

    int bh = blockIdx.y;
    int b = bh >> 4, h = bh & 15;
    int rt = gridDim.x - 1 - blockIdx.x;   // heavy CTAs first
    int q0 = rt * 64;

    int tid = threadIdx.x;
    int lane = tid & 31, wid = tid >> 5;
    int g = lane >> 2, c = lane & 3;
    int wbase = wid * 16;

    const size_t kvstride = 3 * EE;

    auto load_tile = [&](int buf, int st) {
        const float* Kg = qkv + ((size_t)(b * TT + st * 64)) * kvstride + EE + (size_t)h * HD;
        const float* Vg = Kg + EE;
        #pragma unroll
        for (int i = 0; i < 8; i++) {
            int idx = i * 128 + tid;
            int r = idx >> 4, ch = (idx & 15) * 4;
            cp16(&KP[buf][r][ch], Kg + (size_t)r * kvstride + ch);
            cp16(&Vs[buf][r][ch], Vg + (size_t)r * kvstride + ch);
        }
        cp_commit();
    };

    // prefetch tile 0, then build Q fragments while it flies
    load_tile(0, 0);

    uint32_t qf[8][4];
    const float* Qb = qkv + ((size_t)(b * TT + q0 + wbase)) * kvstride + (size_t)h * HD;
    #pragma unroll
    for (int k8 = 0; k8 < 8; k8++) {
        int kb = k8 * 8;
        qf[k8][0] = cvt_tf32(0.125f * Qb[(size_t)g       * kvstride + kb + c]);
        qf[k8][1] = cvt_tf32(0.125f * Qb[(size_t)(g + 8) * kvstride + kb + c]);
        qf[k8][2] = cvt_tf32(0.125f * Qb[(size_t)g       * kvstride + kb + c + 4]);
        qf[k8][3] = cvt_tf32(0.125f * Qb[(size_t)(g + 8) * kvstride + kb + c + 4]);
    }

    float m0 = -INFINITY, m1 = -INFINITY, l0 = 0.f, l1 = 0.f;
    float oacc[8][4];
    #pragma unroll
    for (int nt = 0; nt < 8; nt++)
        #pragma unroll
        for (int k = 0; k < 4; k++) oacc[nt][k] = 0.f;

    for (int st = 0; st <= rt; st++) {
        int cur = st & 1, nxt = cur ^ 1;

        __syncthreads();              // all warps done with buffer nxt (PV of st-1)
        if (st + 1 <= rt) { load_tile(nxt, st + 1); cp_wait<1>(); }
        else              { cp_wait<0>(); }
        __syncthreads();              // tile st visible to everyone

        // S = Q @ K^T
        float sacc[8][4];
        #pragma unroll
        for (int nt = 0; nt < 8; nt++)
            #pragma unroll
            for (int k = 0; k < 4; k++) sacc[nt][k] = 0.f;

        #pragma unroll
        for (int k8 = 0; k8 < 8; k8++) {
            int kb = k8 * 8;
            #pragma unroll
            for (int nt = 0; nt < 8; nt++) {
                uint32_t b0 = cvt_tf32(KP[cur][nt * 8 + g][kb + c]);
                uint32_t b1 = cvt_tf32(KP[cur][nt * 8 + g][kb + c + 4]);
                mma_tf32(sacc[nt], qf[k8], b0, b1);
            }
        }

        // causal mask on diagonal tile only
        if (st == rt) {
            int ql0 = wbase + g, ql1 = ql0 + 8;
            #pragma unroll
            for (int nt = 0; nt < 8; nt++) {
                int kl = nt * 8 + 2 * c;
                if (kl     > ql0) sacc[nt][0] = -1e30f;
                if (kl + 1 > ql0) sacc[nt][1] = -1e30f;
                if (kl     > ql1) sacc[nt][2] = -1e30f;
                if (kl + 1 > ql1) sacc[nt][3] = -1e30f;
            }
        }

        // online softmax
        float mx0 = -1e30f, mx1 = -1e30f;
        #pragma unroll
        for (int nt = 0; nt < 8; nt++) {
            mx0 = fmaxf(mx0, fmaxf(sacc[nt][0], sacc[nt][1]));
            mx1 = fmaxf(mx1, fmaxf(sacc[nt][2], sacc[nt][3]));
        }
        mx0 = fmaxf(mx0, __shfl_xor_sync(0xffffffffu, mx0, 1));
        mx0 = fmaxf(mx0, __shfl_xor_sync(0xffffffffu, mx0, 2));
        mx1 = fmaxf(mx1, __shfl_xor_sync(0xffffffffu, mx1, 1));
        mx1 = fmaxf(mx1, __shfl_xor_sync(0xffffffffu, mx1, 2));

        float mn0 = fmaxf(m0, mx0), mn1 = fmaxf(m1, mx1);
        float al0 = __expf(m0 - mn0), al1 = __expf(m1 - mn1);
        m0 = mn0; m1 = mn1;

        float rs0 = 0.f, rs1 = 0.f;
        #pragma unroll
        for (int nt = 0; nt < 8; nt++) {
            float p0 = __expf(sacc[nt][0] - m0);
            float p1 = __expf(sacc[nt][1] - m0);
            float p2 = __expf(sacc[nt][2] - m1);
            float p3 = __expf(sacc[nt][3] - m1);
            sacc[nt][0] = p0; sacc[nt][1] = p1; sacc[nt][2] = p2; sacc[nt][3] = p3;
            rs0 += p0 + p1; rs1 += p2 + p3;
        }
        rs0 += __shfl_xor_sync(0xffffffffu, rs0, 1);
        rs0 += __shfl_xor_sync(0xffffffffu, rs0, 2);
        rs1 += __shfl_xor_sync(0xffffffffu, rs1, 1);
        rs1 += __shfl_xor_sync(0xffffffffu, rs1, 2);
        l0 = l0 * al0 + rs0;
        l1 = l1 * al1 + rs1;

        #pragma unroll
        for (int nt = 0; nt < 8; nt++) {
            oacc[nt][0] *= al0; oacc[nt][1] *= al0;
            oacc[nt][2] *= al1; oacc[nt][3] *= al1;
        }

        // store P into K buffer (cur) — K dead after S-MMA
        __syncthreads();
        #pragma unroll
        for (int nt = 0; nt < 8; nt++) {
            int col = nt * 8 + 2 * c;
            KP[cur][wbase + g    ][col]     = cvt_tf32f(sacc[nt][0]);
            KP[cur][wbase + g    ][col + 1] = cvt_tf32f(sacc[nt][1]);
            KP[cur][wbase + g + 8][col]     = cvt_tf32f(sacc[nt][2]);
            KP[cur][wbase + g + 8][col + 1] = cvt_tf32f(sacc[nt][3]);
        }
        __syncwarp();   // each warp reads only its own 16 P rows

        // O += P @ V
        #pragma unroll
        for (int k8 = 0; k8 < 8; k8++) {
            int kb = k8 * 8;
            uint32_t af[4];
            af[0] = __float_as_uint(KP[cur][wbase + g    ][kb + c]);
            af[1] = __float_as_uint(KP[cur][wbase + g + 8][kb + c]);
            af[2] = __float_as_uint(KP[cur][wbase + g    ][kb + c + 4]);
            af[3] = __float_as_uint(KP[cur][wbase + g + 8][kb + c + 4]);
            #pragma unroll
            for (int nt = 0; nt < 8; nt++) {
                uint32_t b0 = cvt_tf32(Vs[cur][kb + c    ][nt * 8 + g]);
                uint32_t b1 = cvt_tf32(Vs[cur][kb + c + 4][nt * 8 + g]);
                mma_tf32(oacc[nt], af, b0, b1);
            }
        }
    }

    // epilogue: normalize and write O
    float i0 = 1.0f / l0, i1 = 1.0f / l1;
    float* Ob = o + ((size_t)(b * TT + q0 + wbase)) * EE + (size_t)h * HD;
    #pragma unroll
    for (int nt = 0; nt < 8; nt++) {
        int col = nt * 8 + 2 * c;
        *(float2*)&Ob[(size_t)g * EE + col] =
            make_float2(oacc[nt][0] * i0, oacc[nt][1] * i0);
        *(float2*)&Ob[(size_t)(g + 8) * EE + col] =
            make_float2(oacc[nt][2] * i1, oacc[nt][3] * i1);
    }
}

// ---------------- launcher ----------------
extern "C" void kernel_launch(void* const* d_in, const int* in_sizes, int n_in,
                              void* d_out, int out_size)
{
    const float* x      = (const float*)d_in[0];
    const float* wq     = (const float*)d_in[1];
    const float* wk     = (const float*)d_in[2];
    const float* wv     = (const float*)d_in[3];
    const float* w_proj = (const float*)d_in[4];
    const float* b_proj = (const float*)d_in[5];
    const float* gamma1 = (const float*)d_in[6];
    const float* beta1  = (const float*)d_in[7];
    const float* gamma2 = (const float*)d_in[8];
    const float* beta2  = (const float*)d_in[9];
    const float* w1     = (const float*)d_in[10];
    const float* b1     = (const float*)d_in[11];
    const float* w2     = (const float*)d_in[12];
    const float* b2     = (const float*)d_in[13];
    float* out = (float*)d_out;

    float *p_h, *p_wqkv, *p_qkv, *p_o, *p_x2, *p_h2, *p_ffn;
    cudaGetSymbolAddress((void**)&p_h,    g_h);
    cudaGetSymbolAddress((void**)&p_wqkv, g_wqkv);
    cudaGetSymbolAddress((void**)&p_qkv,  g_qkv);
    cudaGetSymbolAddress((void**)&p_o,    g_o);
    cudaGetSymbolAddress((void**)&p_x2,   g_x2);
    cudaGetSymbolAddress((void**)&p_h2,   g_h2);
    cudaGetSymbolAddress((void**)&p_ffn,  g_ffn);

    cudaFuncSetAttribute(mm_tf32<0>, cudaFuncAttributeMaxDynamicSharedMemorySize, MM_SMEM);
    cudaFuncSetAttribute(mm_tf32<2>, cudaFuncAttributeMaxDynamicSharedMemorySize, MM_SMEM);
    cudaFuncSetAttribute(mm_tf32<3>, cudaFuncAttributeMaxDynamicSharedMemorySize, MM_SMEM);
    cudaFuncSetAttribute(flash_kernel, cudaFuncAttributeMaxDynamicSharedMemorySize, FL_SMEM);

    // 1) LN1
    ln_kernel<<<NTOK, 256>>>(x, gamma1, beta1, p_h);
    // 2) pack per-head weights
    pack_w_kernel<<<(3 * EE * EE) / 256, 256>>>(wq, wk, wv, p_wqkv);
    // 3) QKV = h @ Wqkv
    mm_tf32<0><<<dim3(3 * EE / 128, NTOK / 128), 256, MM_SMEM>>>(p_h, p_wqkv, nullptr, nullptr, p_qkv, NTOK, 3 * EE, EE);
    // 4-6) fused flash attention
    flash_kernel<<<dim3(TT / 64, BHN), 128, FL_SMEM>>>(p_qkv, p_o);
    // 7) x2 = h + O @ w_proj + b_proj
    mm_tf32<3><<<dim3(EE / 128, NTOK / 128), 256, MM_SMEM>>>(p_o, w_proj, b_proj, p_h, p_x2, NTOK, EE, EE);
    // 8) LN2
    ln_kernel<<<NTOK, 256>>>(p_x2, gamma2, beta2, p_h2);
    // 9) ffn = relu(h2 @ w1 + b1)
    mm_tf32<2><<<dim3(DFF / 128, NTOK / 128), 256, MM_SMEM>>>(p_h2, w1, b1, nullptr, p_ffn, NTOK, DFF, EE);
    // 10) out = h2 + ffn @ w2 + b2
    mm_tf32<3><<<dim3(EE / 128, NTOK / 128), 256, MM_SMEM>>>(p_ffn, w2, b2, p_h2, out, NTOK, EE, DFF);
}